// round 7
// baseline (speedup 1.0000x reference)
#include <cuda_runtime.h>
#include <cuda_fp16.h>
#include <math.h>
#include <stdint.h>

#define NTOK 4096      // B*S
#define HDIM 1024
#define IDIM 3584
#define NEXP 8

// K-chunk 64, 3-stage cp.async pipeline. Pitches in fp16 halves.
#define AP   72    // A row: 64 k + 8 pad  (36 words -> ldsm banks 4r%32, conflict-free)
#define BP1  136   // ffn1 B row: 128 n + 8
#define BP2  264   // ffn2 B row: 256 n + 8
#define A_ST   (128 * AP)    // 9216 halves / stage
#define B1_ST  (64 * BP1)    // 8704
#define B2_ST  (64 * BP2)    // 16896
// ffn1 smem layout (halves): A stages @0, B1 @27648, B3 @53760. total 79872 h = 159744 B
// ffn2: A @0, B @27648. total 78336 h = 156672 B
#define F1_B1OFF 27648
#define F1_B3OFF 53760
#define F2_BOFF  27648

// ---------------- device scratch (no allocs) ----------------
__device__ int    g_cnt[NEXP];
__device__ int    g_tok[NEXP][NTOK];
__device__ float  g_wt [NEXP][NTOK];
__device__ int    g_texp [NTOK * 2];
__device__ int    g_tslot[NTOK * 2];
__device__ __half g_act [(size_t)NEXP * NTOK * IDIM];   // fp16 activations
__device__ float  g_part[(size_t)NEXP * NTOK * HDIM];   // weight-folded outs
__device__ __half g_w1h[(size_t)NEXP * HDIM * IDIM];
__device__ __half g_w3h[(size_t)NEXP * HDIM * IDIM];
__device__ __half g_w2h[(size_t)NEXP * IDIM * HDIM];
__device__ __half g_xh [(size_t)NTOK * HDIM];

// ---------------- helpers ----------------
__device__ __forceinline__ uint32_t smem_u32(const void* p) {
    uint32_t a;
    asm("{ .reg .u64 t; cvta.to.shared.u64 t, %1; cvt.u32.u64 %0, t; }" : "=r"(a) : "l"(p));
    return a;
}
__device__ __forceinline__ void cpa16(uint32_t dst, const __half* src) {
    asm volatile("cp.async.cg.shared.global [%0], [%1], 16;" :: "r"(dst), "l"(src));
}
#define CP_COMMIT() asm volatile("cp.async.commit_group;" ::: "memory")
#define CP_WAIT1()  asm volatile("cp.async.wait_group 1;" ::: "memory")
__device__ __forceinline__ void ldsm4(uint32_t* r, uint32_t a) {
    asm volatile("ldmatrix.sync.aligned.m8n8.x4.shared.b16 {%0,%1,%2,%3}, [%4];"
                 : "=r"(r[0]), "=r"(r[1]), "=r"(r[2]), "=r"(r[3]) : "r"(a));
}
__device__ __forceinline__ void ldsm4t(uint32_t* r, uint32_t a) {
    asm volatile("ldmatrix.sync.aligned.m8n8.x4.trans.shared.b16 {%0,%1,%2,%3}, [%4];"
                 : "=r"(r[0]), "=r"(r[1]), "=r"(r[2]), "=r"(r[3]) : "r"(a));
}
__device__ __forceinline__ void mma16(float* d, const uint32_t* a, uint32_t b0, uint32_t b1) {
    asm volatile(
        "mma.sync.aligned.m16n8k16.row.col.f32.f16.f16.f32 "
        "{%0,%1,%2,%3},{%4,%5,%6,%7},{%8,%9},{%0,%1,%2,%3};"
        : "+f"(d[0]), "+f"(d[1]), "+f"(d[2]), "+f"(d[3])
        : "r"(a[0]), "r"(a[1]), "r"(a[2]), "r"(a[3]), "r"(b0), "r"(b1));
}

// ---------------------------------------------------------------------------
__global__ void zero_kernel() { if (threadIdx.x < NEXP) g_cnt[threadIdx.x] = 0; }

// float -> half, 4 elements/thread
__global__ void f2h_kernel(const float* __restrict__ src, __half* __restrict__ dst, int n4) {
    int i = blockIdx.x * blockDim.x + threadIdx.x;
    if (i < n4) {
        float4 v = ((const float4*)src)[i];
        __half2 h0 = __floats2half2_rn(v.x, v.y);
        __half2 h1 = __floats2half2_rn(v.z, v.w);
        uint2 u;
        u.x = *reinterpret_cast<uint32_t*>(&h0);
        u.y = *reinterpret_cast<uint32_t*>(&h1);
        ((uint2*)dst)[i] = u;
    }
}

// ---------------------------------------------------------------------------
__global__ void router_kernel(const float* __restrict__ x,
                              const float* __restrict__ gw,
                              float* __restrict__ logits_out) {
    int t = blockIdx.x;
    __shared__ float xs[HDIM];
    __shared__ float lg[NEXP];
    int tid = threadIdx.x;
    for (int i = tid; i < HDIM; i += 256) xs[i] = x[(size_t)t * HDIM + i];
    __syncthreads();
    int w = tid >> 5, lane = tid & 31;
    float s = 0.f;
    for (int k = lane; k < HDIM; k += 32) s += xs[k] * gw[k * NEXP + w];
    #pragma unroll
    for (int o = 16; o; o >>= 1) s += __shfl_xor_sync(0xffffffffu, s, o);
    if (lane == 0) lg[w] = s;
    __syncthreads();
    if (tid == 0) {
        #pragma unroll
        for (int e = 0; e < NEXP; e++) logits_out[(size_t)t * NEXP + e] = lg[e];
        int b0 = 0; float v0 = lg[0];
        #pragma unroll
        for (int e = 1; e < NEXP; e++) if (lg[e] > v0) { v0 = lg[e]; b0 = e; }
        int b1 = -1; float v1 = -INFINITY;
        #pragma unroll
        for (int e = 0; e < NEXP; e++) if (e != b0 && lg[e] > v1) { v1 = lg[e]; b1 = e; }
        float p1  = expf(v1 - v0);
        float inv = 1.0f / (1.0f + p1);
        int p = atomicAdd(&g_cnt[b0], 1);
        g_tok[b0][p] = t; g_wt[b0][p] = inv;
        int q = atomicAdd(&g_cnt[b1], 1);
        g_tok[b1][q] = t; g_wt[b1][q] = p1 * inv;
        g_texp[2 * t] = b0;  g_tslot[2 * t] = p;
        g_texp[2 * t + 1] = b1; g_tslot[2 * t + 1] = q;
    }
}

// ---------------------------------------------------------------------------
// FFN1: CTA 128(M gathered)x128(N)xK64, 512 thr (16 warps, 4Mx4N), warp 32x32
// dual-output. All-fp16 cp.async 3-stage pipeline; inner loop ldmatrix+mma only.
// ---------------------------------------------------------------------------
__global__ __launch_bounds__(512)
void ffn1_mma() {
    extern __shared__ __half smh[];
    __shared__ int toks[128];
    const int tid = threadIdx.x;
    const int e   = blockIdx.z;
    const int cnt = g_cnt[e];
    const int m0  = blockIdx.y * 128;
    if (m0 >= cnt) return;
    const int n0  = blockIdx.x * 128;

    if (tid < 128) {
        int r = m0 + tid;
        toks[tid] = (r < cnt) ? g_tok[e][r] : g_tok[e][0];
    }
    __syncthreads();
    const uint32_t sb = smem_u32(smh);

    // cp.async mappings (per stage: A 1024 chunks, B1/B3 1024 each; 2/thread each)
    const int ca0 = tid, ca1 = tid + 512;
    const int ar0 = ca0 >> 3, af0 = ca0 & 7;
    const int ar1 = ca1 >> 3, af1 = ca1 & 7;
    const __half* aSrc0 = g_xh + (size_t)toks[ar0] * HDIM + af0 * 8;
    const __half* aSrc1 = g_xh + (size_t)toks[ar1] * HDIM + af1 * 8;
    const uint32_t aDst0 = (ar0 * AP + af0 * 8) * 2;
    const uint32_t aDst1 = (ar1 * AP + af1 * 8) * 2;

    const int br0 = ca0 >> 4, bf0 = ca0 & 15;
    const int br1 = ca1 >> 4, bf1 = ca1 & 15;
    const __half* w1b = g_w1h + (size_t)e * HDIM * IDIM + n0;
    const __half* w3b = g_w3h + (size_t)e * HDIM * IDIM + n0;
    const __half* b1Src0 = w1b + (size_t)br0 * IDIM + bf0 * 8;
    const __half* b1Src1 = w1b + (size_t)br1 * IDIM + bf1 * 8;
    const __half* b3Src0 = w3b + (size_t)br0 * IDIM + bf0 * 8;
    const __half* b3Src1 = w3b + (size_t)br1 * IDIM + bf1 * 8;
    const uint32_t bDst0 = (br0 * BP1 + bf0 * 8) * 2;
    const uint32_t bDst1 = (br1 * BP1 + bf1 * 8) * 2;

    // compute mapping
    const int wid = tid >> 5, lane = tid & 31;
    const int wm = (wid >> 2) * 32, wn = (wid & 3) * 32;
    const int g = lane >> 2, t = lane & 3;
    const int rowoff = (lane & 8) + (lane & 7);
    const int khalf  = (lane & 16) >> 1;

    float acc1[2][4][4], acc3[2][4][4];
    #pragma unroll
    for (int i = 0; i < 2; i++)
        #pragma unroll
        for (int j = 0; j < 4; j++)
            #pragma unroll
            for (int c = 0; c < 4; c++) { acc1[i][j][c] = 0.f; acc3[i][j][c] = 0.f; }

    const int NC = HDIM / 64;   // 16
    // prologue: stages 0,1
    #pragma unroll
    for (int s = 0; s < 2; s++) {
        int k0 = s * 64;
        uint32_t aS  = sb + (s * A_ST) * 2;
        uint32_t b1S = sb + (F1_B1OFF + s * B1_ST) * 2;
        uint32_t b3S = sb + (F1_B3OFF + s * B1_ST) * 2;
        cpa16(aS + aDst0, aSrc0 + k0);
        cpa16(aS + aDst1, aSrc1 + k0);
        cpa16(b1S + bDst0, b1Src0 + (size_t)k0 * IDIM);
        cpa16(b1S + bDst1, b1Src1 + (size_t)k0 * IDIM);
        cpa16(b3S + bDst0, b3Src0 + (size_t)k0 * IDIM);
        cpa16(b3S + bDst1, b3Src1 + (size_t)k0 * IDIM);
        CP_COMMIT();
    }

    for (int it = 0; it < NC; it++) {
        CP_WAIT1();
        __syncthreads();
        int nit = it + 2;
        if (nit < NC) {
            int k0 = nit * 64, ns = nit % 3;
            uint32_t aS  = sb + (ns * A_ST) * 2;
            uint32_t b1S = sb + (F1_B1OFF + ns * B1_ST) * 2;
            uint32_t b3S = sb + (F1_B3OFF + ns * B1_ST) * 2;
            cpa16(aS + aDst0, aSrc0 + k0);
            cpa16(aS + aDst1, aSrc1 + k0);
            cpa16(b1S + bDst0, b1Src0 + (size_t)k0 * IDIM);
            cpa16(b1S + bDst1, b1Src1 + (size_t)k0 * IDIM);
            cpa16(b3S + bDst0, b3Src0 + (size_t)k0 * IDIM);
            cpa16(b3S + bDst1, b3Src1 + (size_t)k0 * IDIM);
        }
        CP_COMMIT();

        int st = it % 3;
        uint32_t aS  = sb + (st * A_ST) * 2;
        uint32_t b1S = sb + (F1_B1OFF + st * B1_ST) * 2;
        uint32_t b3S = sb + (F1_B3OFF + st * B1_ST) * 2;
        #pragma unroll
        for (int ks = 0; ks < 4; ks++) {
            uint32_t a0[4], a1[4];
            ldsm4(a0, aS + ((wm + rowoff) * AP + ks * 16 + khalf) * 2);
            ldsm4(a1, aS + ((wm + 16 + rowoff) * AP + ks * 16 + khalf) * 2);
            #pragma unroll
            for (int j = 0; j < 2; j++) {
                uint32_t br[4];
                uint32_t bo = ((ks * 16 + rowoff) * BP1 + wn + j * 16 + khalf) * 2;
                ldsm4t(br, b1S + bo);
                mma16(acc1[0][2 * j],     a0, br[0], br[1]);
                mma16(acc1[1][2 * j],     a1, br[0], br[1]);
                mma16(acc1[0][2 * j + 1], a0, br[2], br[3]);
                mma16(acc1[1][2 * j + 1], a1, br[2], br[3]);
                ldsm4t(br, b3S + bo);
                mma16(acc3[0][2 * j],     a0, br[0], br[1]);
                mma16(acc3[1][2 * j],     a1, br[0], br[1]);
                mma16(acc3[0][2 * j + 1], a0, br[2], br[3]);
                mma16(acc3[1][2 * j + 1], a1, br[2], br[3]);
            }
        }
    }

    // epilogue: G = silu(D1) * D3 -> fp16
    #pragma unroll
    for (int mt = 0; mt < 2; mt++) {
        int r0 = wm + mt * 16 + g;
        int r1 = r0 + 8;
        bool ok0 = (m0 + r0) < cnt, ok1 = (m0 + r1) < cnt;
        __half* G0 = g_act + ((size_t)e * NTOK + m0 + r0) * IDIM + n0;
        __half* G1 = g_act + ((size_t)e * NTOK + m0 + r1) * IDIM + n0;
        #pragma unroll
        for (int nt = 0; nt < 4; nt++) {
            int cc = wn + nt * 8 + 2 * t;
            if (ok0) {
                float v0 = acc1[mt][nt][0], v1 = acc1[mt][nt][1];
                float o0 = v0 / (1.0f + __expf(-v0)) * acc3[mt][nt][0];
                float o1 = v1 / (1.0f + __expf(-v1)) * acc3[mt][nt][1];
                *(__half2*)(G0 + cc) = __floats2half2_rn(o0, o1);
            }
            if (ok1) {
                float v2 = acc1[mt][nt][2], v3 = acc1[mt][nt][3];
                float o2 = v2 / (1.0f + __expf(-v2)) * acc3[mt][nt][2];
                float o3 = v3 / (1.0f + __expf(-v3)) * acc3[mt][nt][3];
                *(__half2*)(G1 + cc) = __floats2half2_rn(o2, o3);
            }
        }
    }
}

// ---------------------------------------------------------------------------
// FFN2: CTA 128(M)x256(N)xK64, 512 thr (16 warps, 4Mx4N), warp 32x64.
// A = g_act fp16, B = g_w2h fp16 via cp.async. P = wt*(G.w2) into g_part.
// ---------------------------------------------------------------------------
__global__ __launch_bounds__(512)
void ffn2_mma() {
    extern __shared__ __half smh[];
    __shared__ float wts[128];
    const int tid = threadIdx.x;
    const int e   = blockIdx.z;
    const int cnt = g_cnt[e];
    const int m0  = blockIdx.y * 128;
    if (m0 >= cnt) return;
    const int n0  = blockIdx.x * 256;

    if (tid < 128) {
        int r = m0 + tid;
        wts[tid] = (r < cnt) ? g_wt[e][r] : 0.0f;
    }
    __syncthreads();
    const uint32_t sb = smem_u32(smh);

    // A chunks: 1024/stage -> 2/thread
    const int ca0 = tid, ca1 = tid + 512;
    const int ar0 = ca0 >> 3, af0 = ca0 & 7;
    const int ar1 = ca1 >> 3, af1 = ca1 & 7;
    const __half* ga = g_act + ((size_t)e * NTOK + m0) * IDIM;
    const __half* aSrc0 = ga + (size_t)ar0 * IDIM + af0 * 8;
    const __half* aSrc1 = ga + (size_t)ar1 * IDIM + af1 * 8;
    const uint32_t aDst0 = (ar0 * AP + af0 * 8) * 2;
    const uint32_t aDst1 = (ar1 * AP + af1 * 8) * 2;
    // B chunks: 2048/stage -> 4/thread; row=c>>5 (0..63), f=c&31
    const __half* w2b = g_w2h + (size_t)e * IDIM * HDIM + n0;
    const __half* bSrc[4];
    uint32_t bDst[4];
    #pragma unroll
    for (int s = 0; s < 4; s++) {
        int c = tid + s * 512;
        int row = c >> 5, f = c & 31;
        bSrc[s] = w2b + (size_t)row * HDIM + f * 8;
        bDst[s] = (row * BP2 + f * 8) * 2;
    }

    const int wid = tid >> 5, lane = tid & 31;
    const int wm = (wid >> 2) * 32, wn = (wid & 3) * 64;
    const int g = lane >> 2, t = lane & 3;
    const int rowoff = (lane & 8) + (lane & 7);
    const int khalf  = (lane & 16) >> 1;

    float acc[2][8][4];
    #pragma unroll
    for (int i = 0; i < 2; i++)
        #pragma unroll
        for (int j = 0; j < 8; j++)
            #pragma unroll
            for (int c = 0; c < 4; c++) acc[i][j][c] = 0.f;

    const int NC = IDIM / 64;   // 56
    #pragma unroll
    for (int s = 0; s < 2; s++) {
        int k0 = s * 64;
        uint32_t aS = sb + (s * A_ST) * 2;
        uint32_t bS = sb + (F2_BOFF + s * B2_ST) * 2;
        cpa16(aS + aDst0, aSrc0 + k0);
        cpa16(aS + aDst1, aSrc1 + k0);
        #pragma unroll
        for (int q = 0; q < 4; q++) cpa16(bS + bDst[q], bSrc[q] + (size_t)k0 * HDIM);
        CP_COMMIT();
    }

    for (int it = 0; it < NC; it++) {
        CP_WAIT1();
        __syncthreads();
        int nit = it + 2;
        if (nit < NC) {
            int k0 = nit * 64, ns = nit % 3;
            uint32_t aS = sb + (ns * A_ST) * 2;
            uint32_t bS = sb + (F2_BOFF + ns * B2_ST) * 2;
            cpa16(aS + aDst0, aSrc0 + k0);
            cpa16(aS + aDst1, aSrc1 + k0);
            #pragma unroll
            for (int q = 0; q < 4; q++) cpa16(bS + bDst[q], bSrc[q] + (size_t)k0 * HDIM);
        }
        CP_COMMIT();

        int st = it % 3;
        uint32_t aS = sb + (st * A_ST) * 2;
        uint32_t bS = sb + (F2_BOFF + st * B2_ST) * 2;
        #pragma unroll
        for (int ks = 0; ks < 4; ks++) {
            uint32_t a0[4], a1[4];
            ldsm4(a0, aS + ((wm + rowoff) * AP + ks * 16 + khalf) * 2);
            ldsm4(a1, aS + ((wm + 16 + rowoff) * AP + ks * 16 + khalf) * 2);
            #pragma unroll
            for (int j = 0; j < 4; j++) {
                uint32_t br[4];
                ldsm4t(br, bS + ((ks * 16 + rowoff) * BP2 + wn + j * 16 + khalf) * 2);
                mma16(acc[0][2 * j],     a0, br[0], br[1]);
                mma16(acc[1][2 * j],     a1, br[0], br[1]);
                mma16(acc[0][2 * j + 1], a0, br[2], br[3]);
                mma16(acc[1][2 * j + 1], a1, br[2], br[3]);
            }
        }
    }

    #pragma unroll
    for (int mt = 0; mt < 2; mt++) {
        int r0 = wm + mt * 16 + g;
        int r1 = r0 + 8;
        bool ok0 = (m0 + r0) < cnt, ok1 = (m0 + r1) < cnt;
        float w0 = wts[r0], w1v = wts[r1];
        float* P0 = g_part + ((size_t)e * NTOK + m0 + r0) * HDIM + n0;
        float* P1 = g_part + ((size_t)e * NTOK + m0 + r1) * HDIM + n0;
        #pragma unroll
        for (int nt = 0; nt < 8; nt++) {
            int cc = wn + nt * 8 + 2 * t;
            if (ok0) *(float2*)(P0 + cc) = make_float2(w0 * acc[mt][nt][0], w0 * acc[mt][nt][1]);
            if (ok1) *(float2*)(P1 + cc) = make_float2(w1v * acc[mt][nt][2], w1v * acc[mt][nt][3]);
        }
    }
}

// ---------------------------------------------------------------------------
__global__ void combine_kernel(float* __restrict__ out) {
    int t  = blockIdx.x;
    int e0 = g_texp[2 * t],     s0 = g_tslot[2 * t];
    int e1 = g_texp[2 * t + 1], s1 = g_tslot[2 * t + 1];
    const float4* P0 = (const float4*)(g_part + ((size_t)e0 * NTOK + s0) * HDIM);
    const float4* P1 = (const float4*)(g_part + ((size_t)e1 * NTOK + s1) * HDIM);
    float4* O = (float4*)(out + (size_t)t * HDIM);
    int i = threadIdx.x;
    float4 a = P0[i], b = P1[i];
    O[i] = make_float4(a.x + b.x, a.y + b.y, a.z + b.z, a.w + b.w);
}

// ---------------------------------------------------------------------------
extern "C" void kernel_launch(void* const* d_in, const int* in_sizes, int n_in,
                              void* d_out, int out_size) {
    const float* x  = (const float*)d_in[0];
    const float* gw = (const float*)d_in[1];
    const float* w1 = (const float*)d_in[2];
    const float* w3 = (const float*)d_in[3];
    const float* w2 = (const float*)d_in[4];
    float* out = (float*)d_out;
    float* logits = out + ((size_t)out_size - (size_t)NTOK * NEXP);

    const int SMEM1 = (3 * A_ST + 6 * B1_ST) * 2;   // 159744 B
    const int SMEM2 = (3 * A_ST + 3 * B2_ST) * 2;   // 156672 B
    cudaFuncSetAttribute(ffn1_mma, cudaFuncAttributeMaxDynamicSharedMemorySize, SMEM1);
    cudaFuncSetAttribute(ffn2_mma, cudaFuncAttributeMaxDynamicSharedMemorySize, SMEM2);

    __half *w1h_p, *w3h_p, *w2h_p, *xh_p;
    cudaGetSymbolAddress((void**)&w1h_p, g_w1h);
    cudaGetSymbolAddress((void**)&w3h_p, g_w3h);
    cudaGetSymbolAddress((void**)&w2h_p, g_w2h);
    cudaGetSymbolAddress((void**)&xh_p,  g_xh);

    zero_kernel<<<1, 32>>>();
    const int NW4 = NEXP * HDIM * IDIM / 4;   // 7340032
    f2h_kernel<<<(NW4 + 255) / 256, 256>>>(w1, w1h_p, NW4);
    f2h_kernel<<<(NW4 + 255) / 256, 256>>>(w3, w3h_p, NW4);
    f2h_kernel<<<(NW4 + 255) / 256, 256>>>(w2, w2h_p, NW4);
    const int NX4 = NTOK * HDIM / 4;          // 1048576
    f2h_kernel<<<(NX4 + 255) / 256, 256>>>(x, xh_p, NX4);

    router_kernel<<<NTOK, 256>>>(x, gw, logits);

    dim3 g1(IDIM / 128, NTOK / 128, NEXP);
    ffn1_mma<<<g1, 512, SMEM1>>>();

    dim3 g2(HDIM / 256, NTOK / 128, NEXP);
    ffn2_mma<<<g2, 512, SMEM2>>>();

    combine_kernel<<<NTOK, 256>>>(out);
}

// round 8
// speedup vs baseline: 1.5137x; 1.5137x over previous
#include <cuda_runtime.h>
#include <cuda_fp16.h>
#include <math.h>
#include <stdint.h>

#define NTOK 4096      // B*S
#define HDIM 1024
#define IDIM 3584
#define NEXP 8

// smem pitches in fp16 halves (all ldsm phases conflict-free)
#define AP  40    // A row: 32 k + 8 pad
#define BP1 136   // ffn1 B row: 128 n + 8
#define BP2 264   // ffn2 B row: 256 n + 8
#define A_H   (128 * AP)    // 5120 halves / stage
#define B1_H  (32 * BP1)    // 4352
#define B2_H  (32 * BP2)    // 8448

// ---------------- device scratch (no allocs) ----------------
__device__ int    g_cnt[NEXP];
__device__ int    g_tok[NEXP][NTOK];
__device__ float  g_wt [NEXP][NTOK];
__device__ int    g_texp [NTOK * 2];
__device__ int    g_tslot[NTOK * 2];
__device__ __half g_act [(size_t)NEXP * NTOK * IDIM];   // fp16 activations
__device__ float  g_part[(size_t)NEXP * NTOK * HDIM];   // weight-folded outs

// ---------------- helpers ----------------
__device__ __forceinline__ uint32_t smem_u32(const void* p) {
    uint32_t a;
    asm("{ .reg .u64 t; cvta.to.shared.u64 t, %1; cvt.u32.u64 %0, t; }" : "=r"(a) : "l"(p));
    return a;
}
__device__ __forceinline__ void sts_h4(uint32_t addr, float4 v) {
    __half2 h0 = __floats2half2_rn(v.x, v.y);
    __half2 h1 = __floats2half2_rn(v.z, v.w);
    uint32_t u0 = *reinterpret_cast<uint32_t*>(&h0);
    uint32_t u1 = *reinterpret_cast<uint32_t*>(&h1);
    asm volatile("st.shared.v2.b32 [%0], {%1,%2};" :: "r"(addr), "r"(u0), "r"(u1) : "memory");
}
__device__ __forceinline__ void sts_u2(uint32_t addr, uint2 v) {
    asm volatile("st.shared.v2.b32 [%0], {%1,%2};" :: "r"(addr), "r"(v.x), "r"(v.y) : "memory");
}
__device__ __forceinline__ void ldsm4(uint32_t* r, uint32_t a) {
    asm volatile("ldmatrix.sync.aligned.m8n8.x4.shared.b16 {%0,%1,%2,%3}, [%4];"
                 : "=r"(r[0]), "=r"(r[1]), "=r"(r[2]), "=r"(r[3]) : "r"(a));
}
__device__ __forceinline__ void ldsm4t(uint32_t* r, uint32_t a) {
    asm volatile("ldmatrix.sync.aligned.m8n8.x4.trans.shared.b16 {%0,%1,%2,%3}, [%4];"
                 : "=r"(r[0]), "=r"(r[1]), "=r"(r[2]), "=r"(r[3]) : "r"(a));
}
__device__ __forceinline__ void mma16(float* d, const uint32_t* a, uint32_t b0, uint32_t b1) {
    asm volatile(
        "mma.sync.aligned.m16n8k16.row.col.f32.f16.f16.f32 "
        "{%0,%1,%2,%3},{%4,%5,%6,%7},{%8,%9},{%0,%1,%2,%3};"
        : "+f"(d[0]), "+f"(d[1]), "+f"(d[2]), "+f"(d[3])
        : "r"(a[0]), "r"(a[1]), "r"(a[2]), "r"(a[3]), "r"(b0), "r"(b1));
}

// ---------------------------------------------------------------------------
__global__ void zero_kernel() { if (threadIdx.x < NEXP) g_cnt[threadIdx.x] = 0; }

// ---------------------------------------------------------------------------
__global__ void router_kernel(const float* __restrict__ x,
                              const float* __restrict__ gw,
                              float* __restrict__ logits_out) {
    int t = blockIdx.x;
    __shared__ float xs[HDIM];
    __shared__ float lg[NEXP];
    int tid = threadIdx.x;
    for (int i = tid; i < HDIM; i += 256) xs[i] = x[(size_t)t * HDIM + i];
    __syncthreads();
    int w = tid >> 5, lane = tid & 31;
    float s = 0.f;
    for (int k = lane; k < HDIM; k += 32) s += xs[k] * gw[k * NEXP + w];
    #pragma unroll
    for (int o = 16; o; o >>= 1) s += __shfl_xor_sync(0xffffffffu, s, o);
    if (lane == 0) lg[w] = s;
    __syncthreads();
    if (tid == 0) {
        #pragma unroll
        for (int e = 0; e < NEXP; e++) logits_out[(size_t)t * NEXP + e] = lg[e];
        int b0 = 0; float v0 = lg[0];
        #pragma unroll
        for (int e = 1; e < NEXP; e++) if (lg[e] > v0) { v0 = lg[e]; b0 = e; }
        int b1 = -1; float v1 = -INFINITY;
        #pragma unroll
        for (int e = 0; e < NEXP; e++) if (e != b0 && lg[e] > v1) { v1 = lg[e]; b1 = e; }
        float p1  = expf(v1 - v0);
        float inv = 1.0f / (1.0f + p1);
        int p = atomicAdd(&g_cnt[b0], 1);
        g_tok[b0][p] = t; g_wt[b0][p] = inv;
        int q = atomicAdd(&g_cnt[b1], 1);
        g_tok[b1][q] = t; g_wt[b1][q] = p1 * inv;
        g_texp[2 * t] = b0;  g_tslot[2 * t] = p;
        g_texp[2 * t + 1] = b1; g_tslot[2 * t + 1] = q;
    }
}

// ---------------------------------------------------------------------------
// FFN1: CTA 128(M)x128(N)xK32, 256 thr (8 warps, 2Mx4N), warp 64x32 dual.
// fp16 mma m16n8k16 + ldmatrix; G = silu(X.w1)*(X.w3) stored fp16.
// ---------------------------------------------------------------------------
__global__ __launch_bounds__(256, 1)
void ffn1_mma(const float* __restrict__ x,
              const float* __restrict__ w1,
              const float* __restrict__ w3) {
    extern __shared__ __half smh[];
    __shared__ int toks[128];
    const int tid = threadIdx.x;
    const int e   = blockIdx.z;
    const int cnt = g_cnt[e];
    const int m0  = blockIdx.y * 128;
    if (m0 >= cnt) return;
    const int n0  = blockIdx.x * 128;

    if (tid < 128) {
        int r = m0 + tid;
        toks[tid] = (r < cnt) ? g_tok[e][r] : g_tok[e][0];
    }
    __syncthreads();
    const uint32_t sb = smem_u32(smh);
    const uint32_t oB1 = 2 * A_H * 2;
    const uint32_t oB3 = (2 * A_H + 2 * B1_H) * 2;

    // staging: A 4 float4/thread (rows ra+32s), B1/B3 4 float4 each (k-rows kb+8s)
    const int fa = tid & 7,  ra = tid >> 3;    // ra 0..31
    const int fb = tid & 31, kb = tid >> 5;    // kb 0..7
    const float* ap[4];
    #pragma unroll
    for (int s = 0; s < 4; s++)
        ap[s] = x + (size_t)toks[ra + 32 * s] * HDIM + fa * 4;
    const float* W1 = w1 + (size_t)e * HDIM * IDIM + n0 + fb * 4;
    const float* W3 = w3 + (size_t)e * HDIM * IDIM + n0 + fb * 4;
    uint32_t dA[4], dB[4];
    #pragma unroll
    for (int s = 0; s < 4; s++) {
        dA[s] = ((ra + 32 * s) * AP + fa * 4) * 2;
        dB[s] = ((kb + 8 * s) * BP1 + fb * 4) * 2;
    }

    // compute mapping: 8 warps, 2Mx4N, warp 64x32
    const int wid = tid >> 5, lane = tid & 31;
    const int wm = (wid >> 2) * 64, wn = (wid & 3) * 32;
    const int g = lane >> 2, t = lane & 3;
    const int rowoff = (lane & 8) + (lane & 7);
    const int khalf  = (lane & 16) >> 1;

    float acc1[4][4][4], acc3[4][4][4];
    #pragma unroll
    for (int i = 0; i < 4; i++)
        #pragma unroll
        for (int j = 0; j < 4; j++)
            #pragma unroll
            for (int c = 0; c < 4; c++) { acc1[i][j][c] = 0.f; acc3[i][j][c] = 0.f; }

    float4 rA[4], r1[4], r3[4];
    #pragma unroll
    for (int s = 0; s < 4; s++) {
        rA[s] = *(const float4*)(ap[s]);
        r1[s] = *(const float4*)(W1 + (size_t)(kb + 8 * s) * IDIM);
        r3[s] = *(const float4*)(W3 + (size_t)(kb + 8 * s) * IDIM);
    }

    const int NC = HDIM / 32;   // 32
    for (int it = 0; it < NC; it++) {
        int p = it & 1;
        uint32_t aS  = sb + p * (A_H * 2);
        uint32_t b1S = sb + oB1 + p * (B1_H * 2);
        uint32_t b3S = sb + oB3 + p * (B1_H * 2);
        #pragma unroll
        for (int s = 0; s < 4; s++) {
            sts_h4(aS + dA[s], rA[s]);
            sts_h4(b1S + dB[s], r1[s]);
            sts_h4(b3S + dB[s], r3[s]);
        }
        __syncthreads();
        if (it + 1 < NC) {
            int k0 = (it + 1) * 32;
            #pragma unroll
            for (int s = 0; s < 4; s++) {
                rA[s] = *(const float4*)(ap[s] + k0);
                r1[s] = *(const float4*)(W1 + (size_t)(k0 + kb + 8 * s) * IDIM);
                r3[s] = *(const float4*)(W3 + (size_t)(k0 + kb + 8 * s) * IDIM);
            }
        }
        #pragma unroll
        for (int ks = 0; ks < 2; ks++) {
            uint32_t af[4][4];
            #pragma unroll
            for (int mt = 0; mt < 4; mt++)
                ldsm4(af[mt], aS + ((wm + mt * 16 + rowoff) * AP + ks * 16 + khalf) * 2);
            #pragma unroll
            for (int j = 0; j < 2; j++) {
                uint32_t br[4];
                uint32_t bo = ((ks * 16 + rowoff) * BP1 + wn + j * 16 + khalf) * 2;
                ldsm4t(br, b1S + bo);
                #pragma unroll
                for (int mt = 0; mt < 4; mt++) {
                    mma16(acc1[mt][2 * j],     af[mt], br[0], br[1]);
                    mma16(acc1[mt][2 * j + 1], af[mt], br[2], br[3]);
                }
                ldsm4t(br, b3S + bo);
                #pragma unroll
                for (int mt = 0; mt < 4; mt++) {
                    mma16(acc3[mt][2 * j],     af[mt], br[0], br[1]);
                    mma16(acc3[mt][2 * j + 1], af[mt], br[2], br[3]);
                }
            }
        }
        __syncthreads();
    }

    // epilogue: G = silu(D1) * D3 -> fp16
    #pragma unroll
    for (int mt = 0; mt < 4; mt++) {
        int r0 = wm + mt * 16 + g;
        int r1i = r0 + 8;
        bool ok0 = (m0 + r0) < cnt, ok1 = (m0 + r1i) < cnt;
        __half* G0 = g_act + ((size_t)e * NTOK + m0 + r0) * IDIM + n0;
        __half* G1 = g_act + ((size_t)e * NTOK + m0 + r1i) * IDIM + n0;
        #pragma unroll
        for (int nt = 0; nt < 4; nt++) {
            int cc = wn + nt * 8 + 2 * t;
            if (ok0) {
                float v0 = acc1[mt][nt][0], v1 = acc1[mt][nt][1];
                float o0 = v0 / (1.0f + __expf(-v0)) * acc3[mt][nt][0];
                float o1 = v1 / (1.0f + __expf(-v1)) * acc3[mt][nt][1];
                *(__half2*)(G0 + cc) = __floats2half2_rn(o0, o1);
            }
            if (ok1) {
                float v2 = acc1[mt][nt][2], v3 = acc1[mt][nt][3];
                float o2 = v2 / (1.0f + __expf(-v2)) * acc3[mt][nt][2];
                float o3 = v3 / (1.0f + __expf(-v3)) * acc3[mt][nt][3];
                *(__half2*)(G1 + cc) = __floats2half2_rn(o2, o3);
            }
        }
    }
}

// ---------------------------------------------------------------------------
// FFN2: CTA 128(M)x256(N)xK32, 256 thr (8 warps, 2Mx4N), warp 64x64.
// A = g_act (fp16), B = w2 (fp32->fp16 at STS). P = wt*(G.w2).
// ---------------------------------------------------------------------------
__global__ __launch_bounds__(256, 1)
void ffn2_mma(const float* __restrict__ w2) {
    extern __shared__ __half smh[];
    __shared__ float wts[128];
    const int tid = threadIdx.x;
    const int e   = blockIdx.z;
    const int cnt = g_cnt[e];
    const int m0  = blockIdx.y * 128;
    if (m0 >= cnt) return;
    const int n0  = blockIdx.x * 256;

    if (tid < 128) {
        int r = m0 + tid;
        wts[tid] = (r < cnt) ? g_wt[e][r] : 0.0f;
    }
    __syncthreads();
    const uint32_t sb = smem_u32(smh);
    const uint32_t oB = 2 * A_H * 2;

    // staging: A fp16 4 uint2/thread (rows ra+32s); B fp32 8 float4/thread
    const int fa = tid & 7,  ra = tid >> 3;    // ra 0..31
    const int fb = tid & 63, kb = tid >> 6;    // kb 0..3
    const __half* ga = g_act + ((size_t)e * NTOK + m0) * IDIM;
    const __half* ap[4];
    uint32_t dA[4];
    #pragma unroll
    for (int s = 0; s < 4; s++) {
        ap[s] = ga + (size_t)(ra + 32 * s) * IDIM + fa * 4;
        dA[s] = ((ra + 32 * s) * AP + fa * 4) * 2;
    }
    const float* Wb = w2 + (size_t)e * IDIM * HDIM + n0 + fb * 4;
    uint32_t dB[8];
    #pragma unroll
    for (int s = 0; s < 8; s++) dB[s] = ((kb + 4 * s) * BP2 + fb * 4) * 2;

    const int wid = tid >> 5, lane = tid & 31;
    const int wm = (wid >> 2) * 64, wn = (wid & 3) * 64;
    const int g = lane >> 2, t = lane & 3;
    const int rowoff = (lane & 8) + (lane & 7);
    const int khalf  = (lane & 16) >> 1;

    float acc[4][8][4];
    #pragma unroll
    for (int i = 0; i < 4; i++)
        #pragma unroll
        for (int j = 0; j < 8; j++)
            #pragma unroll
            for (int c = 0; c < 4; c++) acc[i][j][c] = 0.f;

    uint2 rA[4];
    float4 rB[8];
    #pragma unroll
    for (int s = 0; s < 4; s++) rA[s] = *(const uint2*)(ap[s]);
    #pragma unroll
    for (int s = 0; s < 8; s++)
        rB[s] = *(const float4*)(Wb + (size_t)(kb + 4 * s) * HDIM);

    const int NC = IDIM / 32;   // 112
    for (int it = 0; it < NC; it++) {
        int p = it & 1;
        uint32_t aS = sb + p * (A_H * 2);
        uint32_t bS = sb + oB + p * (B2_H * 2);
        #pragma unroll
        for (int s = 0; s < 4; s++) sts_u2(aS + dA[s], rA[s]);
        #pragma unroll
        for (int s = 0; s < 8; s++) sts_h4(bS + dB[s], rB[s]);
        __syncthreads();
        if (it + 1 < NC) {
            int k0 = (it + 1) * 32;
            #pragma unroll
            for (int s = 0; s < 4; s++) rA[s] = *(const uint2*)(ap[s] + k0);
            #pragma unroll
            for (int s = 0; s < 8; s++)
                rB[s] = *(const float4*)(Wb + (size_t)(k0 + kb + 4 * s) * HDIM);
        }
        #pragma unroll
        for (int ks = 0; ks < 2; ks++) {
            uint32_t af[4][4];
            #pragma unroll
            for (int mt = 0; mt < 4; mt++)
                ldsm4(af[mt], aS + ((wm + mt * 16 + rowoff) * AP + ks * 16 + khalf) * 2);
            #pragma unroll
            for (int j = 0; j < 4; j++) {
                uint32_t br[4];
                ldsm4t(br, bS + ((ks * 16 + rowoff) * BP2 + wn + j * 16 + khalf) * 2);
                #pragma unroll
                for (int mt = 0; mt < 4; mt++) {
                    mma16(acc[mt][2 * j],     af[mt], br[0], br[1]);
                    mma16(acc[mt][2 * j + 1], af[mt], br[2], br[3]);
                }
            }
        }
        __syncthreads();
    }

    #pragma unroll
    for (int mt = 0; mt < 4; mt++) {
        int r0 = wm + mt * 16 + g;
        int r1 = r0 + 8;
        bool ok0 = (m0 + r0) < cnt, ok1 = (m0 + r1) < cnt;
        float w0 = wts[r0], w1v = wts[r1];
        float* P0 = g_part + ((size_t)e * NTOK + m0 + r0) * HDIM + n0;
        float* P1 = g_part + ((size_t)e * NTOK + m0 + r1) * HDIM + n0;
        #pragma unroll
        for (int nt = 0; nt < 8; nt++) {
            int cc = wn + nt * 8 + 2 * t;
            if (ok0) *(float2*)(P0 + cc) = make_float2(w0 * acc[mt][nt][0], w0 * acc[mt][nt][1]);
            if (ok1) *(float2*)(P1 + cc) = make_float2(w1v * acc[mt][nt][2], w1v * acc[mt][nt][3]);
        }
    }
}

// ---------------------------------------------------------------------------
__global__ void combine_kernel(float* __restrict__ out) {
    int t  = blockIdx.x;
    int e0 = g_texp[2 * t],     s0 = g_tslot[2 * t];
    int e1 = g_texp[2 * t + 1], s1 = g_tslot[2 * t + 1];
    const float4* P0 = (const float4*)(g_part + ((size_t)e0 * NTOK + s0) * HDIM);
    const float4* P1 = (const float4*)(g_part + ((size_t)e1 * NTOK + s1) * HDIM);
    float4* O = (float4*)(out + (size_t)t * HDIM);
    int i = threadIdx.x;
    float4 a = P0[i], b = P1[i];
    O[i] = make_float4(a.x + b.x, a.y + b.y, a.z + b.z, a.w + b.w);
}

// ---------------------------------------------------------------------------
extern "C" void kernel_launch(void* const* d_in, const int* in_sizes, int n_in,
                              void* d_out, int out_size) {
    const float* x  = (const float*)d_in[0];
    const float* gw = (const float*)d_in[1];
    const float* w1 = (const float*)d_in[2];
    const float* w3 = (const float*)d_in[3];
    const float* w2 = (const float*)d_in[4];
    float* out = (float*)d_out;
    float* logits = out + ((size_t)out_size - (size_t)NTOK * NEXP);

    const int SMEM1 = (2 * A_H + 4 * B1_H) * 2;  // 55296 B
    const int SMEM2 = (2 * A_H + 2 * B2_H) * 2;  // 54272 B
    cudaFuncSetAttribute(ffn1_mma, cudaFuncAttributeMaxDynamicSharedMemorySize, SMEM1);
    cudaFuncSetAttribute(ffn2_mma, cudaFuncAttributeMaxDynamicSharedMemorySize, SMEM2);

    zero_kernel<<<1, 32>>>();
    router_kernel<<<NTOK, 256>>>(x, gw, logits);

    dim3 g1(IDIM / 128, NTOK / 128, NEXP);
    ffn1_mma<<<g1, 256, SMEM1>>>(x, w1, w3);

    dim3 g2(HDIM / 256, NTOK / 128, NEXP);
    ffn2_mma<<<g2, 256, SMEM2>>>(w2);

    combine_kernel<<<NTOK, 256>>>(out);
}

// round 9
// speedup vs baseline: 1.5710x; 1.0379x over previous
#include <cuda_runtime.h>
#include <cuda_fp16.h>
#include <math.h>
#include <stdint.h>

#define NTOK 4096      // B*S
#define HDIM 1024
#define IDIM 3584
#define NEXP 8

// smem pitches in fp16 halves (all ldsm phases conflict-free)
#define AP  40    // A row: 32 k + 8 pad
#define BP1 136   // ffn1 B row: 128 n + 8
#define BP2 264   // ffn2 B row: 256 n + 8
#define A_H   (128 * AP)    // 5120 halves / stage
#define B1_H  (32 * BP1)    // 4352
#define B2_H  (32 * BP2)    // 8448

// ---------------- device scratch (no allocs) ----------------
__device__ int    g_cnt[NEXP];
__device__ int    g_tok[NEXP][NTOK];
__device__ float  g_wt [NEXP][NTOK];
__device__ __half g_act [(size_t)NEXP * NTOK * IDIM];   // fp16 activations

// ---------------- helpers ----------------
__device__ __forceinline__ uint32_t smem_u32(const void* p) {
    uint32_t a;
    asm("{ .reg .u64 t; cvta.to.shared.u64 t, %1; cvt.u32.u64 %0, t; }" : "=r"(a) : "l"(p));
    return a;
}
__device__ __forceinline__ void sts_h4(uint32_t addr, float4 v) {
    __half2 h0 = __floats2half2_rn(v.x, v.y);
    __half2 h1 = __floats2half2_rn(v.z, v.w);
    uint32_t u0 = *reinterpret_cast<uint32_t*>(&h0);
    uint32_t u1 = *reinterpret_cast<uint32_t*>(&h1);
    asm volatile("st.shared.v2.b32 [%0], {%1,%2};" :: "r"(addr), "r"(u0), "r"(u1) : "memory");
}
__device__ __forceinline__ void sts_u2(uint32_t addr, uint2 v) {
    asm volatile("st.shared.v2.b32 [%0], {%1,%2};" :: "r"(addr), "r"(v.x), "r"(v.y) : "memory");
}
__device__ __forceinline__ void ldsm4(uint32_t* r, uint32_t a) {
    asm volatile("ldmatrix.sync.aligned.m8n8.x4.shared.b16 {%0,%1,%2,%3}, [%4];"
                 : "=r"(r[0]), "=r"(r[1]), "=r"(r[2]), "=r"(r[3]) : "r"(a));
}
__device__ __forceinline__ void ldsm4t(uint32_t* r, uint32_t a) {
    asm volatile("ldmatrix.sync.aligned.m8n8.x4.trans.shared.b16 {%0,%1,%2,%3}, [%4];"
                 : "=r"(r[0]), "=r"(r[1]), "=r"(r[2]), "=r"(r[3]) : "r"(a));
}
__device__ __forceinline__ void mma16(float* d, const uint32_t* a, uint32_t b0, uint32_t b1) {
    asm volatile(
        "mma.sync.aligned.m16n8k16.row.col.f32.f16.f16.f32 "
        "{%0,%1,%2,%3},{%4,%5,%6,%7},{%8,%9},{%0,%1,%2,%3};"
        : "+f"(d[0]), "+f"(d[1]), "+f"(d[2]), "+f"(d[3])
        : "r"(a[0]), "r"(a[1]), "r"(a[2]), "r"(a[3]), "r"(b0), "r"(b1));
}

// ---------------------------------------------------------------------------
// zero: counters + hidden-state region of out (logits overwritten by router)
// ---------------------------------------------------------------------------
__global__ void zero_kernel(float4* __restrict__ out, int n4) {
    int i = blockIdx.x * blockDim.x + threadIdx.x;
    if (i < n4) out[i] = make_float4(0.f, 0.f, 0.f, 0.f);
    if (i < NEXP) g_cnt[i] = 0;
}

// ---------------------------------------------------------------------------
__global__ void router_kernel(const float* __restrict__ x,
                              const float* __restrict__ gw,
                              float* __restrict__ logits_out) {
    int t = blockIdx.x;
    __shared__ float xs[HDIM];
    __shared__ float lg[NEXP];
    int tid = threadIdx.x;
    for (int i = tid; i < HDIM; i += 256) xs[i] = x[(size_t)t * HDIM + i];
    __syncthreads();
    int w = tid >> 5, lane = tid & 31;
    float s = 0.f;
    for (int k = lane; k < HDIM; k += 32) s += xs[k] * gw[k * NEXP + w];
    #pragma unroll
    for (int o = 16; o; o >>= 1) s += __shfl_xor_sync(0xffffffffu, s, o);
    if (lane == 0) lg[w] = s;
    __syncthreads();
    if (tid == 0) {
        #pragma unroll
        for (int e = 0; e < NEXP; e++) logits_out[(size_t)t * NEXP + e] = lg[e];
        int b0 = 0; float v0 = lg[0];
        #pragma unroll
        for (int e = 1; e < NEXP; e++) if (lg[e] > v0) { v0 = lg[e]; b0 = e; }
        int b1 = -1; float v1 = -INFINITY;
        #pragma unroll
        for (int e = 0; e < NEXP; e++) if (e != b0 && lg[e] > v1) { v1 = lg[e]; b1 = e; }
        float p1  = expf(v1 - v0);
        float inv = 1.0f / (1.0f + p1);
        int p = atomicAdd(&g_cnt[b0], 1);
        g_tok[b0][p] = t; g_wt[b0][p] = inv;
        int q = atomicAdd(&g_cnt[b1], 1);
        g_tok[b1][q] = t; g_wt[b1][q] = p1 * inv;
    }
}

// ---------------------------------------------------------------------------
// FFN1: CTA 128(M)x128(N)xK32, 256 thr (8 warps, 2Mx4N), warp 64x32 dual.
// fp16 mma m16n8k16 + ldmatrix; G = silu(X.w1)*(X.w3) stored fp16.
// Single barrier per K-chunk (double-buffer safe).
// ---------------------------------------------------------------------------
__global__ __launch_bounds__(256, 1)
void ffn1_mma(const float* __restrict__ x,
              const float* __restrict__ w1,
              const float* __restrict__ w3) {
    extern __shared__ __half smh[];
    __shared__ int toks[128];
    const int tid = threadIdx.x;
    const int e   = blockIdx.z;
    const int cnt = g_cnt[e];
    const int m0  = blockIdx.y * 128;
    if (m0 >= cnt) return;
    const int n0  = blockIdx.x * 128;

    if (tid < 128) {
        int r = m0 + tid;
        toks[tid] = (r < cnt) ? g_tok[e][r] : g_tok[e][0];
    }
    __syncthreads();
    const uint32_t sb = smem_u32(smh);
    const uint32_t oB1 = 2 * A_H * 2;
    const uint32_t oB3 = (2 * A_H + 2 * B1_H) * 2;

    const int fa = tid & 7,  ra = tid >> 3;    // ra 0..31
    const int fb = tid & 31, kb = tid >> 5;    // kb 0..7
    const float* ap[4];
    #pragma unroll
    for (int s = 0; s < 4; s++)
        ap[s] = x + (size_t)toks[ra + 32 * s] * HDIM + fa * 4;
    const float* W1 = w1 + (size_t)e * HDIM * IDIM + n0 + fb * 4;
    const float* W3 = w3 + (size_t)e * HDIM * IDIM + n0 + fb * 4;
    uint32_t dA[4], dB[4];
    #pragma unroll
    for (int s = 0; s < 4; s++) {
        dA[s] = ((ra + 32 * s) * AP + fa * 4) * 2;
        dB[s] = ((kb + 8 * s) * BP1 + fb * 4) * 2;
    }

    const int wid = tid >> 5, lane = tid & 31;
    const int wm = (wid >> 2) * 64, wn = (wid & 3) * 32;
    const int g = lane >> 2, t = lane & 3;
    const int rowoff = (lane & 8) + (lane & 7);
    const int khalf  = (lane & 16) >> 1;

    float acc1[4][4][4], acc3[4][4][4];
    #pragma unroll
    for (int i = 0; i < 4; i++)
        #pragma unroll
        for (int j = 0; j < 4; j++)
            #pragma unroll
            for (int c = 0; c < 4; c++) { acc1[i][j][c] = 0.f; acc3[i][j][c] = 0.f; }

    float4 rA[4], r1[4], r3[4];
    #pragma unroll
    for (int s = 0; s < 4; s++) {
        rA[s] = *(const float4*)(ap[s]);
        r1[s] = *(const float4*)(W1 + (size_t)(kb + 8 * s) * IDIM);
        r3[s] = *(const float4*)(W3 + (size_t)(kb + 8 * s) * IDIM);
    }

    const int NC = HDIM / 32;   // 32
    for (int it = 0; it < NC; it++) {
        int p = it & 1;
        uint32_t aS  = sb + p * (A_H * 2);
        uint32_t b1S = sb + oB1 + p * (B1_H * 2);
        uint32_t b3S = sb + oB3 + p * (B1_H * 2);
        #pragma unroll
        for (int s = 0; s < 4; s++) {
            sts_h4(aS + dA[s], rA[s]);
            sts_h4(b1S + dB[s], r1[s]);
            sts_h4(b3S + dB[s], r3[s]);
        }
        __syncthreads();
        if (it + 1 < NC) {
            int k0 = (it + 1) * 32;
            #pragma unroll
            for (int s = 0; s < 4; s++) {
                rA[s] = *(const float4*)(ap[s] + k0);
                r1[s] = *(const float4*)(W1 + (size_t)(k0 + kb + 8 * s) * IDIM);
                r3[s] = *(const float4*)(W3 + (size_t)(k0 + kb + 8 * s) * IDIM);
            }
        }
        #pragma unroll
        for (int ks = 0; ks < 2; ks++) {
            uint32_t af[4][4];
            #pragma unroll
            for (int mt = 0; mt < 4; mt++)
                ldsm4(af[mt], aS + ((wm + mt * 16 + rowoff) * AP + ks * 16 + khalf) * 2);
            #pragma unroll
            for (int j = 0; j < 2; j++) {
                uint32_t br[4];
                uint32_t bo = ((ks * 16 + rowoff) * BP1 + wn + j * 16 + khalf) * 2;
                ldsm4t(br, b1S + bo);
                #pragma unroll
                for (int mt = 0; mt < 4; mt++) {
                    mma16(acc1[mt][2 * j],     af[mt], br[0], br[1]);
                    mma16(acc1[mt][2 * j + 1], af[mt], br[2], br[3]);
                }
                ldsm4t(br, b3S + bo);
                #pragma unroll
                for (int mt = 0; mt < 4; mt++) {
                    mma16(acc3[mt][2 * j],     af[mt], br[0], br[1]);
                    mma16(acc3[mt][2 * j + 1], af[mt], br[2], br[3]);
                }
            }
        }
    }

    // epilogue: G = silu(D1) * D3 -> fp16
    #pragma unroll
    for (int mt = 0; mt < 4; mt++) {
        int r0 = wm + mt * 16 + g;
        int r1i = r0 + 8;
        bool ok0 = (m0 + r0) < cnt, ok1 = (m0 + r1i) < cnt;
        __half* G0 = g_act + ((size_t)e * NTOK + m0 + r0) * IDIM + n0;
        __half* G1 = g_act + ((size_t)e * NTOK + m0 + r1i) * IDIM + n0;
        #pragma unroll
        for (int nt = 0; nt < 4; nt++) {
            int cc = wn + nt * 8 + 2 * t;
            if (ok0) {
                float v0 = acc1[mt][nt][0], v1 = acc1[mt][nt][1];
                float o0 = v0 / (1.0f + __expf(-v0)) * acc3[mt][nt][0];
                float o1 = v1 / (1.0f + __expf(-v1)) * acc3[mt][nt][1];
                *(__half2*)(G0 + cc) = __floats2half2_rn(o0, o1);
            }
            if (ok1) {
                float v2 = acc1[mt][nt][2], v3 = acc1[mt][nt][3];
                float o2 = v2 / (1.0f + __expf(-v2)) * acc3[mt][nt][2];
                float o3 = v3 / (1.0f + __expf(-v3)) * acc3[mt][nt][3];
                *(__half2*)(G1 + cc) = __floats2half2_rn(o2, o3);
            }
        }
    }
}

// ---------------------------------------------------------------------------
// FFN2: CTA 128(M)x256(N)xK32, 256 thr (8 warps, 2Mx4N), warp 64x64.
// A = g_act (fp16), B = w2 (fp32->fp16 at STS). out[tok] += wt*(G.w2) via
// atomicAdd (exactly 2 commutative adds per element -> deterministic).
// ---------------------------------------------------------------------------
__global__ __launch_bounds__(256, 1)
void ffn2_mma(const float* __restrict__ w2, float* __restrict__ out) {
    extern __shared__ __half smh[];
    __shared__ float wts[128];
    __shared__ int   tk2[128];
    const int tid = threadIdx.x;
    const int e   = blockIdx.z;
    const int cnt = g_cnt[e];
    const int m0  = blockIdx.y * 128;
    if (m0 >= cnt) return;
    const int n0  = blockIdx.x * 256;

    if (tid < 128) {
        int r = m0 + tid;
        bool ok = r < cnt;
        wts[tid] = ok ? g_wt[e][r] : 0.0f;
        tk2[tid] = ok ? g_tok[e][r] : 0;
    }
    __syncthreads();
    const uint32_t sb = smem_u32(smh);
    const uint32_t oB = 2 * A_H * 2;

    const int fa = tid & 7,  ra = tid >> 3;    // ra 0..31
    const int fb = tid & 63, kb = tid >> 6;    // kb 0..3
    const __half* ga = g_act + ((size_t)e * NTOK + m0) * IDIM;
    const __half* ap[4];
    uint32_t dA[4];
    #pragma unroll
    for (int s = 0; s < 4; s++) {
        ap[s] = ga + (size_t)(ra + 32 * s) * IDIM + fa * 4;
        dA[s] = ((ra + 32 * s) * AP + fa * 4) * 2;
    }
    const float* Wb = w2 + (size_t)e * IDIM * HDIM + n0 + fb * 4;
    uint32_t dB[8];
    #pragma unroll
    for (int s = 0; s < 8; s++) dB[s] = ((kb + 4 * s) * BP2 + fb * 4) * 2;

    const int wid = tid >> 5, lane = tid & 31;
    const int wm = (wid >> 2) * 64, wn = (wid & 3) * 64;
    const int g = lane >> 2, t = lane & 3;
    const int rowoff = (lane & 8) + (lane & 7);
    const int khalf  = (lane & 16) >> 1;

    float acc[4][8][4];
    #pragma unroll
    for (int i = 0; i < 4; i++)
        #pragma unroll
        for (int j = 0; j < 8; j++)
            #pragma unroll
            for (int c = 0; c < 4; c++) acc[i][j][c] = 0.f;

    uint2 rA[4];
    float4 rB[8];
    #pragma unroll
    for (int s = 0; s < 4; s++) rA[s] = *(const uint2*)(ap[s]);
    #pragma unroll
    for (int s = 0; s < 8; s++)
        rB[s] = *(const float4*)(Wb + (size_t)(kb + 4 * s) * HDIM);

    const int NC = IDIM / 32;   // 112
    for (int it = 0; it < NC; it++) {
        int p = it & 1;
        uint32_t aS = sb + p * (A_H * 2);
        uint32_t bS = sb + oB + p * (B2_H * 2);
        #pragma unroll
        for (int s = 0; s < 4; s++) sts_u2(aS + dA[s], rA[s]);
        #pragma unroll
        for (int s = 0; s < 8; s++) sts_h4(bS + dB[s], rB[s]);
        __syncthreads();
        if (it + 1 < NC) {
            int k0 = (it + 1) * 32;
            #pragma unroll
            for (int s = 0; s < 4; s++) rA[s] = *(const uint2*)(ap[s] + k0);
            #pragma unroll
            for (int s = 0; s < 8; s++)
                rB[s] = *(const float4*)(Wb + (size_t)(k0 + kb + 4 * s) * HDIM);
        }
        #pragma unroll
        for (int ks = 0; ks < 2; ks++) {
            uint32_t af[4][4];
            #pragma unroll
            for (int mt = 0; mt < 4; mt++)
                ldsm4(af[mt], aS + ((wm + mt * 16 + rowoff) * AP + ks * 16 + khalf) * 2);
            #pragma unroll
            for (int j = 0; j < 4; j++) {
                uint32_t br[4];
                ldsm4t(br, bS + ((ks * 16 + rowoff) * BP2 + wn + j * 16 + khalf) * 2);
                #pragma unroll
                for (int mt = 0; mt < 4; mt++) {
                    mma16(acc[mt][2 * j],     af[mt], br[0], br[1]);
                    mma16(acc[mt][2 * j + 1], af[mt], br[2], br[3]);
                }
            }
        }
    }

    // epilogue: out[tok] += wt * acc  (atomic, 2 adds/element total)
    #pragma unroll
    for (int mt = 0; mt < 4; mt++) {
        int r0 = wm + mt * 16 + g;
        int r1 = r0 + 8;
        bool ok0 = (m0 + r0) < cnt, ok1 = (m0 + r1) < cnt;
        float w0 = wts[r0], w1v = wts[r1];
        float* O0 = out + (size_t)tk2[r0] * HDIM + n0;
        float* O1 = out + (size_t)tk2[r1] * HDIM + n0;
        #pragma unroll
        for (int nt = 0; nt < 8; nt++) {
            int cc = wn + nt * 8 + 2 * t;
            if (ok0) {
                atomicAdd(&O0[cc],     w0 * acc[mt][nt][0]);
                atomicAdd(&O0[cc + 1], w0 * acc[mt][nt][1]);
            }
            if (ok1) {
                atomicAdd(&O1[cc],     w1v * acc[mt][nt][2]);
                atomicAdd(&O1[cc + 1], w1v * acc[mt][nt][3]);
            }
        }
    }
}

// ---------------------------------------------------------------------------
extern "C" void kernel_launch(void* const* d_in, const int* in_sizes, int n_in,
                              void* d_out, int out_size) {
    const float* x  = (const float*)d_in[0];
    const float* gw = (const float*)d_in[1];
    const float* w1 = (const float*)d_in[2];
    const float* w3 = (const float*)d_in[3];
    const float* w2 = (const float*)d_in[4];
    float* out = (float*)d_out;
    float* logits = out + ((size_t)out_size - (size_t)NTOK * NEXP);

    const int SMEM1 = (2 * A_H + 4 * B1_H) * 2;  // 55296 B
    const int SMEM2 = (2 * A_H + 2 * B2_H) * 2;  // 54272 B
    cudaFuncSetAttribute(ffn1_mma, cudaFuncAttributeMaxDynamicSharedMemorySize, SMEM1);
    cudaFuncSetAttribute(ffn2_mma, cudaFuncAttributeMaxDynamicSharedMemorySize, SMEM2);

    const int NZ4 = NTOK * HDIM / 4;   // 1048576 float4
    zero_kernel<<<(NZ4 + 255) / 256, 256>>>((float4*)out, NZ4);
    router_kernel<<<NTOK, 256>>>(x, gw, logits);

    dim3 g1(IDIM / 128, NTOK / 128, NEXP);
    ffn1_mma<<<g1, 256, SMEM1>>>(x, w1, w3);

    dim3 g2(HDIM / 256, NTOK / 128, NEXP);
    ffn2_mma<<<g2, 256, SMEM2>>>(w2, out);
}